// round 4
// baseline (speedup 1.0000x reference)
#include <cuda_runtime.h>
#include <math.h>

// Problem constants
#define BB 32
#define TT 256
#define EE 256
#define HH 512
#define G4 2048          // 4*H
#define VV 32000
#define BT 8192          // B*T

// ---------------------------------------------------------------------------
// Scratch (no allocations allowed -> __device__ globals)
// ---------------------------------------------------------------------------
__device__ int g_idx[BT];
__device__ float g_xg[(size_t)BT * G4];   // [t][b][4H] input-gate preactivations
__device__ float g_hs[(size_t)BT * HH];   // [t][b][H] hidden states
__device__ unsigned g_bar_count = 0;
__device__ volatile unsigned g_bar_gen = 0;

// ---------------------------------------------------------------------------
// Token index decode: handles both int64 and int32 storage of x
// ---------------------------------------------------------------------------
__global__ void decode_idx_kernel(const void* __restrict__ xin) {
    int i = blockIdx.x * blockDim.x + threadIdx.x;
    if (i >= BT) return;
    const long long* x64 = (const long long*)xin;
    bool is64 = true;
#pragma unroll
    for (int j = 0; j < 8; j++) {
        long long v = x64[j];
        if (v < 0 || v >= VV) is64 = false;
    }
    g_idx[i] = is64 ? (int)x64[i] : ((const int*)xin)[i];
}

// ---------------------------------------------------------------------------
// Packed f32x2 helpers (FFMA2 path: 2x fp32 FMA throughput vs FFMA-3reg)
// ---------------------------------------------------------------------------
__device__ __forceinline__ unsigned long long pk2(float x, float y) {
    unsigned long long r;
    asm("mov.b64 %0, {%1, %2};" : "=l"(r) : "f"(x), "f"(y));
    return r;
}
__device__ __forceinline__ void upk2(unsigned long long v, float& x, float& y) {
    asm("mov.b64 {%0, %1}, %2;" : "=f"(x), "=f"(y) : "l"(v));
}
__device__ __forceinline__ void fma2(unsigned long long& d, unsigned long long a,
                                     unsigned long long b) {
    asm("fma.rn.f32x2 %0, %1, %2, %3;" : "=l"(d) : "l"(a), "l"(b), "l"(d));
}

// ---------------------------------------------------------------------------
// Tiled NT SGEMM: C[m][n] = sum_k A[m][k] * W[n][k] + bias[n]
// BM=128, BN=128, BK=16, 256 threads, 8x8 microtile with f32x2 accumulators.
// MODE 0: A = embed_w gathered via g_idx (K=256), out -> g_xg [t][b][4H]
// MODE 1: A = g_hs (row remap), W=fc_w (K=512), out -> d_out [m][V]
// MODE 2: A = g_hs (row remap), W=ln_w (K=512), out -> states [m][H]
// All dims divide tiles exactly; no bounds checks needed.
// ---------------------------------------------------------------------------
template <int MODE>
__global__ __launch_bounds__(256) void gemm_nt_kernel(
    const float* __restrict__ Wm,    // [N][K]
    const float* __restrict__ bias,  // [N]
    const float* __restrict__ Aext,  // embed_w for MODE 0, unused otherwise
    float* __restrict__ outp)        // MODE 1: out, MODE 2: states
{
    constexpr int K = (MODE == 0) ? EE : HH;
    constexpr int NK = K / 16;
    __shared__ float sA[16 * 132];   // [k][m], padded stride 132
    __shared__ float sB[16 * 132];   // [k][n]

    const int tid = threadIdx.x;
    const int tx = tid & 15;
    const int ty = tid >> 4;
    const int bx = blockIdx.x;
    const int by = blockIdx.y;

    const int ldr = tid >> 2;          // 0..63 (row within tile)
    const int ldk = (tid & 3) * 4;     // k offset 0,4,8,12

    // A row base pointers (constant across k loop)
    const int m0 = by * 128 + ldr;
    const int m1 = m0 + 64;
    const float *ap0, *ap1;
    if (MODE == 0) {
        ap0 = Aext + (size_t)g_idx[m0] * EE + ldk;
        ap1 = Aext + (size_t)g_idx[m1] * EE + ldk;
    } else {
        ap0 = g_hs + (size_t)((m0 & 255) * 32 + (m0 >> 8)) * HH + ldk;
        ap1 = g_hs + (size_t)((m1 & 255) * 32 + (m1 >> 8)) * HH + ldk;
    }
    const int n0 = bx * 128 + ldr;
    const float* bp0 = Wm + (size_t)n0 * K + ldk;
    const float* bp1 = Wm + (size_t)(n0 + 64) * K + ldk;

    unsigned long long c2[8][4];
#pragma unroll
    for (int i = 0; i < 8; i++)
#pragma unroll
        for (int j = 0; j < 4; j++) c2[i][j] = 0ull;

    // Stage tile 0 into registers
    float4 pa0 = *(const float4*)ap0;
    float4 pa1 = *(const float4*)ap1;
    float4 pb0 = *(const float4*)bp0;
    float4 pb1 = *(const float4*)bp1;

    for (int kt = 0; kt < NK; kt++) {
        // staged regs -> smem (transposed to [k][m])
#pragma unroll
        for (int j = 0; j < 4; j++) {
            sA[(ldk + j) * 132 + ldr]      = ((const float*)&pa0)[j];
            sA[(ldk + j) * 132 + ldr + 64] = ((const float*)&pa1)[j];
            sB[(ldk + j) * 132 + ldr]      = ((const float*)&pb0)[j];
            sB[(ldk + j) * 132 + ldr + 64] = ((const float*)&pb1)[j];
        }
        __syncthreads();
        // issue next-tile global loads before compute (latency overlap)
        if (kt + 1 < NK) {
            ap0 += 16; ap1 += 16; bp0 += 16; bp1 += 16;
            pa0 = *(const float4*)ap0;
            pa1 = *(const float4*)ap1;
            pb0 = *(const float4*)bp0;
            pb1 = *(const float4*)bp1;
        }
#pragma unroll
        for (int k = 0; k < 16; k++) {
            float4 av0 = *(const float4*)(sA + k * 132 + ty * 8);
            float4 av1 = *(const float4*)(sA + k * 132 + ty * 8 + 4);
            ulonglong2 bq0 = *(const ulonglong2*)(sB + k * 132 + tx * 8);
            ulonglong2 bq1 = *(const ulonglong2*)(sB + k * 132 + tx * 8 + 4);
            unsigned long long aa[8];
            aa[0] = pk2(av0.x, av0.x);
            aa[1] = pk2(av0.y, av0.y);
            aa[2] = pk2(av0.z, av0.z);
            aa[3] = pk2(av0.w, av0.w);
            aa[4] = pk2(av1.x, av1.x);
            aa[5] = pk2(av1.y, av1.y);
            aa[6] = pk2(av1.z, av1.z);
            aa[7] = pk2(av1.w, av1.w);
#pragma unroll
            for (int i = 0; i < 8; i++) {
                fma2(c2[i][0], aa[i], bq0.x);
                fma2(c2[i][1], aa[i], bq0.y);
                fma2(c2[i][2], aa[i], bq1.x);
                fma2(c2[i][3], aa[i], bq1.y);
            }
        }
        __syncthreads();
    }

    // Epilogue: unpack + bias + vectorized store
    const int gn = bx * 128 + tx * 8;
    float4 bv0 = *(const float4*)(bias + gn);
    float4 bv1 = *(const float4*)(bias + gn + 4);
#pragma unroll
    for (int i = 0; i < 8; i++) {
        int gm = by * 128 + ty * 8 + i;
        float* orow;
        if (MODE == 0)
            orow = g_xg + (size_t)((gm & 255) * 32 + (gm >> 8)) * G4 + gn;
        else if (MODE == 1)
            orow = outp + (size_t)gm * VV + gn;
        else
            orow = outp + (size_t)gm * HH + gn;
        float o0, o1, o2, o3, o4, o5, o6, o7;
        upk2(c2[i][0], o0, o1);
        upk2(c2[i][1], o2, o3);
        upk2(c2[i][2], o4, o5);
        upk2(c2[i][3], o6, o7);
        float4 v0 = make_float4(o0 + bv0.x, o1 + bv0.y, o2 + bv0.z, o3 + bv0.w);
        float4 v1 = make_float4(o4 + bv1.x, o5 + bv1.y, o6 + bv1.z, o7 + bv1.w);
        *(float4*)orow = v0;
        *(float4*)(orow + 4) = v1;
    }
}

// ---------------------------------------------------------------------------
// Persistent LSTM kernel: 128 blocks x 256 threads, all co-resident (1/SM).
// Block handles 4 hidden units (16 gate rows). w_hh fragments live in
// registers across all 256 timesteps; h(t-1) is staged in smem each step.
// One grid-wide barrier per step.
// ---------------------------------------------------------------------------
#define LSTM_BLOCKS 128
#define LSTM_SMEM_FLOATS (32 * 512 + 16 * 32 * 16 + 16 * 32 + 4 * 32 + 16)
#define LSTM_SMEM_BYTES (LSTM_SMEM_FLOATS * 4)

__device__ __forceinline__ int lstm_grow(int j0, int r) {
    return (r >> 2) * 512 + j0 + (r & 3);   // gate g = r>>2, unit u = r&3
}

__device__ __forceinline__ void grid_barrier() {
    __threadfence();
    __syncthreads();
    if (threadIdx.x == 0) {
        unsigned gen = g_bar_gen;
        unsigned arr = atomicAdd(&g_bar_count, 1u);
        if (arr == gridDim.x - 1) {
            g_bar_count = 0;
            __threadfence();
            g_bar_gen = gen + 1;
        } else {
            while (g_bar_gen == gen) { }
        }
    }
    __syncthreads();
    __threadfence();
}

__global__ __launch_bounds__(256) void lstm_kernel(const float* __restrict__ w_hh,
                                                   const float* __restrict__ b_hh) {
    extern __shared__ float sm[];
    float* sH    = sm;                          // [32][512]
    float* sRed  = sH + 32 * 512;               // [16 rows][32 b][16 kslices]
    float* sGate = sRed + 16 * 32 * 16;         // [16 rows][32 b]
    float* sC    = sGate + 16 * 32;             // [4 units][32 b]
    float* sBh   = sC + 4 * 32;                 // [16]

    const int tid = threadIdx.x;
    const int bid = blockIdx.x;
    const int j0 = bid * 4;                     // first hidden unit of block
    const int ks = tid & 15;                    // k-slice (interleaved, stride 16)
    const int rp = (tid >> 4) & 7;              // row pair
    const int bh = tid >> 7;                    // batch half (0/1)
    const int r0 = rp * 2, r1 = rp * 2 + 1;

    // Load per-thread weight fragments into registers (persist across t loop)
    float w0[32], w1[32];
    {
        const float* p0 = w_hh + (size_t)lstm_grow(j0, r0) * 512 + ks;
        const float* p1 = w_hh + (size_t)lstm_grow(j0, r1) * 512 + ks;
#pragma unroll
        for (int i = 0; i < 32; i++) {
            w0[i] = p0[i * 16];
            w1[i] = p1[i * 16];
        }
    }
    if (tid < 16) sBh[tid] = b_hh[lstm_grow(j0, tid)];
    if (tid < 128) sC[tid] = 0.f;
    for (int i = tid; i < 32 * 512; i += 256) sH[i] = 0.f;   // h(-1) = 0
    __syncthreads();

    for (int t = 0; t < TT; t++) {
        if (t > 0) {
            const float4* src = (const float4*)(g_hs + (size_t)(t - 1) * 32 * 512);
            float4* dst = (float4*)sH;
#pragma unroll
            for (int i = 0; i < 16; i++) dst[tid + 256 * i] = src[tid + 256 * i];
            __syncthreads();
        }

        // Partial dot products: 2 rows x 16 batches x 32 k-values per thread.
        // sH reads are bank-conflict-free: bank = (ks + 16*i) & 31, lanes with
        // equal ks hit the same address (broadcast).
        float acc0[16], acc1[16];
#pragma unroll
        for (int b = 0; b < 16; b++) { acc0[b] = 0.f; acc1[b] = 0.f; }
#pragma unroll
        for (int i = 0; i < 32; i++) {
            const float* hp = sH + bh * 16 * 512 + ks + 16 * i;
            const float wa = w0[i];
            const float wb = w1[i];
#pragma unroll
            for (int b = 0; b < 16; b++) {
                float hv = hp[b * 512];
                acc0[b] = fmaf(wa, hv, acc0[b]);
                acc1[b] = fmaf(wb, hv, acc1[b]);
            }
        }
#pragma unroll
        for (int b = 0; b < 16; b++) {
            int bb = bh * 16 + b;
            sRed[(r0 * 32 + bb) * 16 + ks] = acc0[b];
            sRed[(r1 * 32 + bb) * 16 + ks] = acc1[b];
        }
        __syncthreads();

        // Reduce 16 k-slice partials per output, add xg + b_hh
#pragma unroll
        for (int o2 = 0; o2 < 2; o2++) {
            int o = tid * 2 + o2;
            int r = o >> 5, b = o & 31;
            const float* pr = sRed + o * 16;
            float s = 0.f;
#pragma unroll
            for (int j = 0; j < 16; j++) s += pr[j];
            s += g_xg[(size_t)(t * 32 + b) * G4 + lstm_grow(j0, r)] + sBh[r];
            sGate[o] = s;
        }
        __syncthreads();

        // Activations + state update (gate order i,f,g,o)
        if (tid < 128) {
            int u = tid & 3, b = tid >> 2;
            float gi = sGate[(0 + u) * 32 + b];
            float gf = sGate[(4 + u) * 32 + b];
            float gg = sGate[(8 + u) * 32 + b];
            float go = sGate[(12 + u) * 32 + b];
            float c = sC[u * 32 + b];
            float si = 1.f / (1.f + expf(-gi));
            float sf = 1.f / (1.f + expf(-gf));
            float so = 1.f / (1.f + expf(-go));
            c = sf * c + si * tanhf(gg);
            float h = so * tanhf(c);
            sC[u * 32 + b] = c;
            g_hs[(size_t)(t * 32 + b) * 512 + j0 + u] = h;
        }
        grid_barrier();
    }
}

// ---------------------------------------------------------------------------
// Launch
// ---------------------------------------------------------------------------
extern "C" void kernel_launch(void* const* d_in, const int* in_sizes, int n_in,
                              void* d_out, int out_size) {
    const void*  x       = d_in[0];
    const float* embed_w = (const float*)d_in[1];
    const float* w_ih    = (const float*)d_in[2];
    const float* w_hh    = (const float*)d_in[3];
    const float* b_ih    = (const float*)d_in[4];
    const float* b_hh    = (const float*)d_in[5];
    const float* fc_w    = (const float*)d_in[6];
    const float* fc_b    = (const float*)d_in[7];
    const float* ln_w    = (const float*)d_in[8];
    const float* ln_b    = (const float*)d_in[9];

    float* out    = (float*)d_out;
    float* states = out + (size_t)BT * VV;

    // 1) decode token indices (int64 or int32 storage)
    decode_idx_kernel<<<BT / 256, 256>>>(x);

    // 2) xg = embed[x] @ w_ih^T + b_ih   -> g_xg [t][b][4H]
    gemm_nt_kernel<0><<<dim3(G4 / 128, BT / 128), 256>>>(w_ih, b_ih, embed_w, nullptr);

    // 3) sequential LSTM over T steps -> g_hs [t][b][H]
    cudaFuncSetAttribute(lstm_kernel, cudaFuncAttributeMaxDynamicSharedMemorySize,
                         LSTM_SMEM_BYTES);
    lstm_kernel<<<LSTM_BLOCKS, 256, LSTM_SMEM_BYTES>>>(w_hh, b_hh);

    // 4) out = hs @ fc_w^T + fc_b   [B*T, V]
    gemm_nt_kernel<1><<<dim3(VV / 128, BT / 128), 256>>>(fc_w, fc_b, nullptr, out);

    // 5) states = hs @ ln_w^T + ln_b   [B*T, H]
    gemm_nt_kernel<2><<<dim3(HH / 128, BT / 128), 256>>>(ln_w, ln_b, nullptr, states);
}

// round 7
// speedup vs baseline: 1.6239x; 1.6239x over previous
#include <cuda_runtime.h>
#include <math.h>
#include <stdint.h>

// Problem constants
#define BB 32
#define TT 256
#define EE 256
#define HH 512
#define G4 2048          // 4*H
#define VV 32000
#define BT 8192          // B*T

// ---------------------------------------------------------------------------
// Scratch (no allocations allowed -> __device__ globals)
// ---------------------------------------------------------------------------
__device__ int g_idx[BT];
__device__ float g_xg[(size_t)BT * G4];   // [t][b][4H] input-gate preactivations
__device__ float g_hs[(size_t)BT * HH];   // [t][b][H] hidden states
__device__ unsigned g_bar_count = 0;
__device__ volatile unsigned g_bar_gen = 0;

// ---------------------------------------------------------------------------
// Token index decode: handles both int64 and int32 storage of x
// ---------------------------------------------------------------------------
__global__ void decode_idx_kernel(const void* __restrict__ xin) {
    int i = blockIdx.x * blockDim.x + threadIdx.x;
    if (i >= BT) return;
    const long long* x64 = (const long long*)xin;
    bool is64 = true;
#pragma unroll
    for (int j = 0; j < 8; j++) {
        long long v = x64[j];
        if (v < 0 || v >= VV) is64 = false;
    }
    g_idx[i] = is64 ? (int)x64[i] : ((const int*)xin)[i];
}

// ---------------------------------------------------------------------------
// Packed f32x2 helpers (FFMA2 path) — used by the SIMT xg GEMM
// ---------------------------------------------------------------------------
__device__ __forceinline__ unsigned long long pk2(float x, float y) {
    unsigned long long r;
    asm("mov.b64 %0, {%1, %2};" : "=l"(r) : "f"(x), "f"(y));
    return r;
}
__device__ __forceinline__ void upk2(unsigned long long v, float& x, float& y) {
    asm("mov.b64 {%0, %1}, %2;" : "=f"(x), "=f"(y) : "l"(v));
}
__device__ __forceinline__ void fma2(unsigned long long& d, unsigned long long a,
                                     unsigned long long b) {
    asm("fma.rn.f32x2 %0, %1, %2, %3;" : "=l"(d) : "l"(a), "l"(b), "l"(d));
}

// ---------------------------------------------------------------------------
// SIMT tiled NT SGEMM — kept only for xg (MODE 0): keeps LSTM inputs fp32.
// ---------------------------------------------------------------------------
__global__ __launch_bounds__(256) void gemm_xg_kernel(
    const float* __restrict__ Wm,    // w_ih [2048][256]
    const float* __restrict__ bias,  // b_ih
    const float* __restrict__ Aext)  // embed_w
{
    constexpr int K = EE;
    constexpr int NK = K / 16;
    __shared__ float sA[16 * 132];
    __shared__ float sB[16 * 132];

    const int tid = threadIdx.x;
    const int tx = tid & 15;
    const int ty = tid >> 4;
    const int bx = blockIdx.x;
    const int by = blockIdx.y;

    const int ldr = tid >> 2;
    const int ldk = (tid & 3) * 4;

    const int m0 = by * 128 + ldr;
    const int m1 = m0 + 64;
    const float* ap0 = Aext + (size_t)g_idx[m0] * EE + ldk;
    const float* ap1 = Aext + (size_t)g_idx[m1] * EE + ldk;
    const int n0 = bx * 128 + ldr;
    const float* bp0 = Wm + (size_t)n0 * K + ldk;
    const float* bp1 = Wm + (size_t)(n0 + 64) * K + ldk;

    unsigned long long c2[8][4];
#pragma unroll
    for (int i = 0; i < 8; i++)
#pragma unroll
        for (int j = 0; j < 4; j++) c2[i][j] = 0ull;

    float4 pa0 = *(const float4*)ap0;
    float4 pa1 = *(const float4*)ap1;
    float4 pb0 = *(const float4*)bp0;
    float4 pb1 = *(const float4*)bp1;

    for (int kt = 0; kt < NK; kt++) {
#pragma unroll
        for (int j = 0; j < 4; j++) {
            sA[(ldk + j) * 132 + ldr]      = ((const float*)&pa0)[j];
            sA[(ldk + j) * 132 + ldr + 64] = ((const float*)&pa1)[j];
            sB[(ldk + j) * 132 + ldr]      = ((const float*)&pb0)[j];
            sB[(ldk + j) * 132 + ldr + 64] = ((const float*)&pb1)[j];
        }
        __syncthreads();
        if (kt + 1 < NK) {
            ap0 += 16; ap1 += 16; bp0 += 16; bp1 += 16;
            pa0 = *(const float4*)ap0;
            pa1 = *(const float4*)ap1;
            pb0 = *(const float4*)bp0;
            pb1 = *(const float4*)bp1;
        }
#pragma unroll
        for (int k = 0; k < 16; k++) {
            float4 av0 = *(const float4*)(sA + k * 132 + ty * 8);
            float4 av1 = *(const float4*)(sA + k * 132 + ty * 8 + 4);
            ulonglong2 bq0 = *(const ulonglong2*)(sB + k * 132 + tx * 8);
            ulonglong2 bq1 = *(const ulonglong2*)(sB + k * 132 + tx * 8 + 4);
            unsigned long long aa[8];
            aa[0] = pk2(av0.x, av0.x);
            aa[1] = pk2(av0.y, av0.y);
            aa[2] = pk2(av0.z, av0.z);
            aa[3] = pk2(av0.w, av0.w);
            aa[4] = pk2(av1.x, av1.x);
            aa[5] = pk2(av1.y, av1.y);
            aa[6] = pk2(av1.z, av1.z);
            aa[7] = pk2(av1.w, av1.w);
#pragma unroll
            for (int i = 0; i < 8; i++) {
                fma2(c2[i][0], aa[i], bq0.x);
                fma2(c2[i][1], aa[i], bq0.y);
                fma2(c2[i][2], aa[i], bq1.x);
                fma2(c2[i][3], aa[i], bq1.y);
            }
        }
        __syncthreads();
    }

    const int gn = bx * 128 + tx * 8;
    float4 bv0 = *(const float4*)(bias + gn);
    float4 bv1 = *(const float4*)(bias + gn + 4);
#pragma unroll
    for (int i = 0; i < 8; i++) {
        int gm = by * 128 + ty * 8 + i;
        float* orow = g_xg + (size_t)((gm & 255) * 32 + (gm >> 8)) * G4 + gn;
        float o0, o1, o2, o3, o4, o5, o6, o7;
        upk2(c2[i][0], o0, o1);
        upk2(c2[i][1], o2, o3);
        upk2(c2[i][2], o4, o5);
        upk2(c2[i][3], o6, o7);
        float4 v0 = make_float4(o0 + bv0.x, o1 + bv0.y, o2 + bv0.z, o3 + bv0.w);
        float4 v1 = make_float4(o4 + bv1.x, o5 + bv1.y, o6 + bv1.z, o7 + bv1.w);
        *(float4*)orow = v0;
        *(float4*)(orow + 4) = v1;
    }
}

// ---------------------------------------------------------------------------
// mma.sync tf32 GEMM (sm_80 baseline PTX — compiles for compute_103):
//   C[m][n] = sum_k A[m][k] * W[n][k] + bias[n]
// A rows come from g_hs with the [t][b] remap. K = 512 fixed.
// CTA 128x128, BK=32, 8 warps (2M x 4N), warp tile 64x32, m16n8k8 frags.
// Smem holds fragments in consumer order: one LDS.128/LDS.64 per fragment.
// OUTLD: row stride of output (VV for fc, HH for ln).
// ---------------------------------------------------------------------------
#define MM_KITERS 16          // 512 / 32
#define MM_SMEM_BYTES 65536   // 2 stages x (16KB A + 16KB B)

__device__ __forceinline__ uint32_t f2tf32(float f) {
    uint32_t r;
    asm("cvt.rna.tf32.f32 %0, %1;" : "=r"(r) : "f"(f));
    return r;
}
__device__ __forceinline__ void mma_tf32(float* c, const uint32_t* a,
                                         const uint32_t* b) {
    asm volatile(
        "mma.sync.aligned.m16n8k8.row.col.f32.tf32.tf32.f32 "
        "{%0,%1,%2,%3}, {%4,%5,%6,%7}, {%8,%9}, {%0,%1,%2,%3};"
        : "+f"(c[0]), "+f"(c[1]), "+f"(c[2]), "+f"(c[3])
        : "r"(a[0]), "r"(a[1]), "r"(a[2]), "r"(a[3]), "r"(b[0]), "r"(b[1]));
}

template <int OUTLD>
__global__ __launch_bounds__(256) void gemm_mma_kernel(
    const float* __restrict__ Wm,    // [N][512]
    const float* __restrict__ bias,  // [N]
    float* __restrict__ outp)
{
    extern __shared__ char smem[];
    const int tid = threadIdx.x;
    const int w = tid >> 5;
    const int lane = tid & 31;
    const int g = lane >> 2;   // groupID
    const int t = lane & 3;    // threadID_in_group
    const int wm = w >> 2;     // 0..1
    const int wn = w & 3;      // 0..3
    const int by = blockIdx.y;
    const int m0 = by * 128;
    const int n0 = blockIdx.x * 128;

    // A gather base: A[m][k] = g_hs[((m&255)*32 + (m>>8))*512 + k]
    // m = m0 + rlocal; linear in rlocal with slope 32*512 floats.
    const float* aBase = g_hs +
        ((size_t)((by & 1) * 128) * 32 + (size_t)(by >> 1)) * 512 +
        (size_t)g * 16384 + t;
    const float* bBase = Wm + (size_t)(n0 + g) * 512 + t;

    // Per-warp staging block constants
    int a_kk[4], a_mb[4];
#pragma unroll
    for (int j = 0; j < 4; j++) {
        int f = w * 4 + j;
        a_kk[j] = f >> 3;
        a_mb[j] = f & 7;
    }
    int b_kk[8], b_nb[8];
#pragma unroll
    for (int j = 0; j < 8; j++) {
        int fb = w * 8 + j;
        b_kk[j] = fb >> 4;
        b_nb[j] = fb & 15;
    }

    float c[4][4][4];
#pragma unroll
    for (int mi = 0; mi < 4; mi++)
#pragma unroll
        for (int ni = 0; ni < 4; ni++)
#pragma unroll
            for (int q = 0; q < 4; q++) c[mi][ni][q] = 0.f;

    float av[4][4], bv[8][2];

    // gather for stage s into av/bv
    auto GATHER = [&](int s) {
        const int k0 = s * 32;
#pragma unroll
        for (int j = 0; j < 4; j++) {
            const float* p = aBase + (size_t)a_mb[j] * 262144 + k0 + 8 * a_kk[j];
            av[j][0] = p[0];
            av[j][1] = p[131072];
            av[j][2] = p[4];
            av[j][3] = p[131072 + 4];
        }
#pragma unroll
        for (int j = 0; j < 8; j++) {
            const float* p = bBase + (size_t)b_nb[j] * 4096 + k0 + 8 * b_kk[j];
            bv[j][0] = p[0];
            bv[j][1] = p[4];
        }
    };
    // cvt + store into smem buffer buf (fragment order)
    auto STORE = [&](int buf) {
        uint32_t* aD = (uint32_t*)(smem + buf * 16384) + (w * 4) * 128 + lane * 4;
        uint32_t* bD = (uint32_t*)(smem + 32768 + buf * 16384) + (w * 8) * 64 + lane * 2;
#pragma unroll
        for (int j = 0; j < 4; j++) {
            uint4 v = make_uint4(f2tf32(av[j][0]), f2tf32(av[j][1]),
                                 f2tf32(av[j][2]), f2tf32(av[j][3]));
            *(uint4*)(aD + j * 128) = v;
        }
#pragma unroll
        for (int j = 0; j < 8; j++) {
            uint2 v = make_uint2(f2tf32(bv[j][0]), f2tf32(bv[j][1]));
            *(uint2*)(bD + j * 64) = v;
        }
    };

    GATHER(0);
    STORE(0);
    __syncthreads();

    for (int s = 0; s < MM_KITERS; s++) {
        const int cur = s & 1;
        if (s + 1 < MM_KITERS) GATHER(s + 1);

        const char* aS = smem + cur * 16384;
        const char* bS = smem + 32768 + cur * 16384;
#pragma unroll
        for (int kk = 0; kk < 4; kk++) {
            uint32_t af[4][4];
#pragma unroll
            for (int mi = 0; mi < 4; mi++) {
                int f = kk * 8 + wm * 4 + mi;
                uint4 v = *(const uint4*)(aS + f * 512 + lane * 16);
                af[mi][0] = v.x; af[mi][1] = v.y; af[mi][2] = v.z; af[mi][3] = v.w;
            }
            uint32_t bf[4][2];
#pragma unroll
            for (int ni = 0; ni < 4; ni++) {
                int fb = kk * 16 + wn * 4 + ni;
                uint2 v = *(const uint2*)(bS + fb * 256 + lane * 8);
                bf[ni][0] = v.x; bf[ni][1] = v.y;
            }
#pragma unroll
            for (int mi = 0; mi < 4; mi++)
#pragma unroll
                for (int ni = 0; ni < 4; ni++)
                    mma_tf32(c[mi][ni], af[mi], bf[ni]);
        }

        if (s + 1 < MM_KITERS) {
            STORE((s + 1) & 1);
            __syncthreads();
        }
    }

    // Epilogue: direct STG.64 with bias
    const int row0 = m0 + wm * 64 + g;
    const int col0 = n0 + wn * 32 + 2 * t;
    float2 bias2[4];
#pragma unroll
    for (int ni = 0; ni < 4; ni++)
        bias2[ni] = *(const float2*)(bias + col0 + ni * 8);
#pragma unroll
    for (int mi = 0; mi < 4; mi++) {
        float* r0 = outp + (size_t)(row0 + mi * 16) * OUTLD;
        float* r1 = outp + (size_t)(row0 + mi * 16 + 8) * OUTLD;
#pragma unroll
        for (int ni = 0; ni < 4; ni++) {
            float2 v0 = make_float2(c[mi][ni][0] + bias2[ni].x,
                                    c[mi][ni][1] + bias2[ni].y);
            float2 v1 = make_float2(c[mi][ni][2] + bias2[ni].x,
                                    c[mi][ni][3] + bias2[ni].y);
            *(float2*)(r0 + col0 + ni * 8) = v0;
            *(float2*)(r1 + col0 + ni * 8) = v1;
        }
    }
}

// ---------------------------------------------------------------------------
// Persistent LSTM kernel (unchanged — correct & ~0.9ms)
// ---------------------------------------------------------------------------
#define LSTM_BLOCKS 128
#define LSTM_SMEM_FLOATS (32 * 512 + 16 * 32 * 16 + 16 * 32 + 4 * 32 + 16)
#define LSTM_SMEM_BYTES (LSTM_SMEM_FLOATS * 4)

__device__ __forceinline__ int lstm_grow(int j0, int r) {
    return (r >> 2) * 512 + j0 + (r & 3);
}

__device__ __forceinline__ void grid_barrier() {
    __threadfence();
    __syncthreads();
    if (threadIdx.x == 0) {
        unsigned gen = g_bar_gen;
        unsigned arr = atomicAdd(&g_bar_count, 1u);
        if (arr == gridDim.x - 1) {
            g_bar_count = 0;
            __threadfence();
            g_bar_gen = gen + 1;
        } else {
            while (g_bar_gen == gen) { }
        }
    }
    __syncthreads();
    __threadfence();
}

__global__ __launch_bounds__(256) void lstm_kernel(const float* __restrict__ w_hh,
                                                   const float* __restrict__ b_hh) {
    extern __shared__ float sm[];
    float* sH    = sm;
    float* sRed  = sH + 32 * 512;
    float* sGate = sRed + 16 * 32 * 16;
    float* sC    = sGate + 16 * 32;
    float* sBh   = sC + 4 * 32;

    const int tid = threadIdx.x;
    const int bid = blockIdx.x;
    const int j0 = bid * 4;
    const int ks = tid & 15;
    const int rp = (tid >> 4) & 7;
    const int bh = tid >> 7;
    const int r0 = rp * 2, r1 = rp * 2 + 1;

    float w0[32], w1[32];
    {
        const float* p0 = w_hh + (size_t)lstm_grow(j0, r0) * 512 + ks;
        const float* p1 = w_hh + (size_t)lstm_grow(j0, r1) * 512 + ks;
#pragma unroll
        for (int i = 0; i < 32; i++) {
            w0[i] = p0[i * 16];
            w1[i] = p1[i * 16];
        }
    }
    if (tid < 16) sBh[tid] = b_hh[lstm_grow(j0, tid)];
    if (tid < 128) sC[tid] = 0.f;
    for (int i = tid; i < 32 * 512; i += 256) sH[i] = 0.f;
    __syncthreads();

    for (int t = 0; t < TT; t++) {
        if (t > 0) {
            const float4* src = (const float4*)(g_hs + (size_t)(t - 1) * 32 * 512);
            float4* dst = (float4*)sH;
#pragma unroll
            for (int i = 0; i < 16; i++) dst[tid + 256 * i] = src[tid + 256 * i];
            __syncthreads();
        }

        float acc0[16], acc1[16];
#pragma unroll
        for (int b = 0; b < 16; b++) { acc0[b] = 0.f; acc1[b] = 0.f; }
#pragma unroll
        for (int i = 0; i < 32; i++) {
            const float* hp = sH + bh * 16 * 512 + ks + 16 * i;
            const float wa = w0[i];
            const float wb = w1[i];
#pragma unroll
            for (int b = 0; b < 16; b++) {
                float hv = hp[b * 512];
                acc0[b] = fmaf(wa, hv, acc0[b]);
                acc1[b] = fmaf(wb, hv, acc1[b]);
            }
        }
#pragma unroll
        for (int b = 0; b < 16; b++) {
            int bb = bh * 16 + b;
            sRed[(r0 * 32 + bb) * 16 + ks] = acc0[b];
            sRed[(r1 * 32 + bb) * 16 + ks] = acc1[b];
        }
        __syncthreads();

#pragma unroll
        for (int o2 = 0; o2 < 2; o2++) {
            int o = tid * 2 + o2;
            int r = o >> 5, b = o & 31;
            const float* pr = sRed + o * 16;
            float s = 0.f;
#pragma unroll
            for (int j = 0; j < 16; j++) s += pr[j];
            s += g_xg[(size_t)(t * 32 + b) * G4 + lstm_grow(j0, r)] + sBh[r];
            sGate[o] = s;
        }
        __syncthreads();

        if (tid < 128) {
            int u = tid & 3, b = tid >> 2;
            float gi = sGate[(0 + u) * 32 + b];
            float gf = sGate[(4 + u) * 32 + b];
            float gg = sGate[(8 + u) * 32 + b];
            float go = sGate[(12 + u) * 32 + b];
            float c = sC[u * 32 + b];
            float si = 1.f / (1.f + expf(-gi));
            float sf = 1.f / (1.f + expf(-gf));
            float so = 1.f / (1.f + expf(-go));
            c = sf * c + si * tanhf(gg);
            float h = so * tanhf(c);
            sC[u * 32 + b] = c;
            g_hs[(size_t)(t * 32 + b) * 512 + j0 + u] = h;
        }
        grid_barrier();
    }
}

// ---------------------------------------------------------------------------
// Launch
// ---------------------------------------------------------------------------
extern "C" void kernel_launch(void* const* d_in, const int* in_sizes, int n_in,
                              void* d_out, int out_size) {
    const void*  x       = d_in[0];
    const float* embed_w = (const float*)d_in[1];
    const float* w_ih    = (const float*)d_in[2];
    const float* w_hh    = (const float*)d_in[3];
    const float* b_ih    = (const float*)d_in[4];
    const float* b_hh    = (const float*)d_in[5];
    const float* fc_w    = (const float*)d_in[6];
    const float* fc_b    = (const float*)d_in[7];
    const float* ln_w    = (const float*)d_in[8];
    const float* ln_b    = (const float*)d_in[9];

    float* out    = (float*)d_out;
    float* states = out + (size_t)BT * VV;

    // 1) decode token indices
    decode_idx_kernel<<<BT / 256, 256>>>(x);

    // 2) xg = embed[x] @ w_ih^T + b_ih   (SIMT fp32, keeps LSTM inputs exact)
    gemm_xg_kernel<<<dim3(G4 / 128, BT / 128), 256>>>(w_ih, b_ih, embed_w);

    // 3) sequential LSTM
    cudaFuncSetAttribute(lstm_kernel, cudaFuncAttributeMaxDynamicSharedMemorySize,
                         LSTM_SMEM_BYTES);
    lstm_kernel<<<LSTM_BLOCKS, 256, LSTM_SMEM_BYTES>>>(w_hh, b_hh);

    // 4) out = hs @ fc_w^T + fc_b   (mma.sync tf32)
    cudaFuncSetAttribute(gemm_mma_kernel<VV>,
                         cudaFuncAttributeMaxDynamicSharedMemorySize, MM_SMEM_BYTES);
    gemm_mma_kernel<VV><<<dim3(VV / 128, BT / 128), 256, MM_SMEM_BYTES>>>(
        fc_w, fc_b, out);

    // 5) states = hs @ ln_w^T + ln_b   (mma.sync tf32)
    cudaFuncSetAttribute(gemm_mma_kernel<HH>,
                         cudaFuncAttributeMaxDynamicSharedMemorySize, MM_SMEM_BYTES);
    gemm_mma_kernel<HH><<<dim3(HH / 128, BT / 128), 256, MM_SMEM_BYTES>>>(
        ln_w, ln_b, states);
}

// round 8
// speedup vs baseline: 2.1702x; 1.3364x over previous
#include <cuda_runtime.h>
#include <math.h>
#include <stdint.h>

// Problem constants
#define BB 32
#define TT 256
#define EE 256
#define HH 512
#define G4 2048          // 4*H
#define VV 32000
#define BT 8192          // B*T

// ---------------------------------------------------------------------------
// Scratch (no allocations allowed -> __device__ globals)
// ---------------------------------------------------------------------------
__device__ int g_idx[BT];
__device__ float g_xg[(size_t)BT * G4];   // [t][b][4H] input-gate preactivations
__device__ float g_hs[(size_t)BT * HH];   // [t][b][H] hidden states
__device__ unsigned g_bar_count = 0;
__device__ volatile unsigned g_bar_gen = 0;

// ---------------------------------------------------------------------------
// Token index decode: handles both int64 and int32 storage of x
// ---------------------------------------------------------------------------
__global__ void decode_idx_kernel(const void* __restrict__ xin) {
    int i = blockIdx.x * blockDim.x + threadIdx.x;
    if (i >= BT) return;
    const long long* x64 = (const long long*)xin;
    bool is64 = true;
#pragma unroll
    for (int j = 0; j < 8; j++) {
        long long v = x64[j];
        if (v < 0 || v >= VV) is64 = false;
    }
    g_idx[i] = is64 ? (int)x64[i] : ((const int*)xin)[i];
}

// ---------------------------------------------------------------------------
// Packed f32x2 helpers (FFMA2 path) — used by the SIMT xg GEMM
// ---------------------------------------------------------------------------
__device__ __forceinline__ unsigned long long pk2(float x, float y) {
    unsigned long long r;
    asm("mov.b64 %0, {%1, %2};" : "=l"(r) : "f"(x), "f"(y));
    return r;
}
__device__ __forceinline__ void upk2(unsigned long long v, float& x, float& y) {
    asm("mov.b64 {%0, %1}, %2;" : "=f"(x), "=f"(y) : "l"(v));
}
__device__ __forceinline__ void fma2(unsigned long long& d, unsigned long long a,
                                     unsigned long long b) {
    asm("fma.rn.f32x2 %0, %1, %2, %3;" : "=l"(d) : "l"(a), "l"(b), "l"(d));
}

// ---------------------------------------------------------------------------
// SIMT tiled NT SGEMM — kept only for xg: keeps LSTM inputs fp32-exact.
// ---------------------------------------------------------------------------
__global__ __launch_bounds__(256) void gemm_xg_kernel(
    const float* __restrict__ Wm,    // w_ih [2048][256]
    const float* __restrict__ bias,  // b_ih
    const float* __restrict__ Aext)  // embed_w
{
    constexpr int K = EE;
    constexpr int NK = K / 16;
    __shared__ float sA[16 * 132];
    __shared__ float sB[16 * 132];

    const int tid = threadIdx.x;
    const int tx = tid & 15;
    const int ty = tid >> 4;
    const int bx = blockIdx.x;
    const int by = blockIdx.y;

    const int ldr = tid >> 2;
    const int ldk = (tid & 3) * 4;

    const int m0 = by * 128 + ldr;
    const int m1 = m0 + 64;
    const float* ap0 = Aext + (size_t)g_idx[m0] * EE + ldk;
    const float* ap1 = Aext + (size_t)g_idx[m1] * EE + ldk;
    const int n0 = bx * 128 + ldr;
    const float* bp0 = Wm + (size_t)n0 * K + ldk;
    const float* bp1 = Wm + (size_t)(n0 + 64) * K + ldk;

    unsigned long long c2[8][4];
#pragma unroll
    for (int i = 0; i < 8; i++)
#pragma unroll
        for (int j = 0; j < 4; j++) c2[i][j] = 0ull;

    float4 pa0 = *(const float4*)ap0;
    float4 pa1 = *(const float4*)ap1;
    float4 pb0 = *(const float4*)bp0;
    float4 pb1 = *(const float4*)bp1;

    for (int kt = 0; kt < NK; kt++) {
#pragma unroll
        for (int j = 0; j < 4; j++) {
            sA[(ldk + j) * 132 + ldr]      = ((const float*)&pa0)[j];
            sA[(ldk + j) * 132 + ldr + 64] = ((const float*)&pa1)[j];
            sB[(ldk + j) * 132 + ldr]      = ((const float*)&pb0)[j];
            sB[(ldk + j) * 132 + ldr + 64] = ((const float*)&pb1)[j];
        }
        __syncthreads();
        if (kt + 1 < NK) {
            ap0 += 16; ap1 += 16; bp0 += 16; bp1 += 16;
            pa0 = *(const float4*)ap0;
            pa1 = *(const float4*)ap1;
            pb0 = *(const float4*)bp0;
            pb1 = *(const float4*)bp1;
        }
#pragma unroll
        for (int k = 0; k < 16; k++) {
            float4 av0 = *(const float4*)(sA + k * 132 + ty * 8);
            float4 av1 = *(const float4*)(sA + k * 132 + ty * 8 + 4);
            ulonglong2 bq0 = *(const ulonglong2*)(sB + k * 132 + tx * 8);
            ulonglong2 bq1 = *(const ulonglong2*)(sB + k * 132 + tx * 8 + 4);
            unsigned long long aa[8];
            aa[0] = pk2(av0.x, av0.x);
            aa[1] = pk2(av0.y, av0.y);
            aa[2] = pk2(av0.z, av0.z);
            aa[3] = pk2(av0.w, av0.w);
            aa[4] = pk2(av1.x, av1.x);
            aa[5] = pk2(av1.y, av1.y);
            aa[6] = pk2(av1.z, av1.z);
            aa[7] = pk2(av1.w, av1.w);
#pragma unroll
            for (int i = 0; i < 8; i++) {
                fma2(c2[i][0], aa[i], bq0.x);
                fma2(c2[i][1], aa[i], bq0.y);
                fma2(c2[i][2], aa[i], bq1.x);
                fma2(c2[i][3], aa[i], bq1.y);
            }
        }
        __syncthreads();
    }

    const int gn = bx * 128 + tx * 8;
    float4 bv0 = *(const float4*)(bias + gn);
    float4 bv1 = *(const float4*)(bias + gn + 4);
#pragma unroll
    for (int i = 0; i < 8; i++) {
        int gm = by * 128 + ty * 8 + i;
        float* orow = g_xg + (size_t)((gm & 255) * 32 + (gm >> 8)) * G4 + gn;
        float o0, o1, o2, o3, o4, o5, o6, o7;
        upk2(c2[i][0], o0, o1);
        upk2(c2[i][1], o2, o3);
        upk2(c2[i][2], o4, o5);
        upk2(c2[i][3], o6, o7);
        float4 v0 = make_float4(o0 + bv0.x, o1 + bv0.y, o2 + bv0.z, o3 + bv0.w);
        float4 v1 = make_float4(o4 + bv1.x, o5 + bv1.y, o6 + bv1.z, o7 + bv1.w);
        *(float4*)orow = v0;
        *(float4*)(orow + 4) = v1;
    }
}

// ---------------------------------------------------------------------------
// mma.sync tf32 GEMM (sm_80 baseline PTX), l1tex-optimized staging:
//   C[m][n] = sum_k A[m][k] * W[n][k] + bias[n],  K = 512
// CTA 128x128, BK=32, 8 warps (2M x 4N), warp tile 64x32, m16n8k8.
// Tiles stored ROW-MAJOR in smem with 36-float padded stride:
//   - LDG.128 fully coalesced (1 line per tile-row)
//   - STS.128 conflict-free (contiguous per 8-lane phase)
//   - consumer LDS.32: bank = (g*4 + t + C) & 31 -> conflict-free
// OUTLD: row stride of output (VV for fc, HH for ln).
// ---------------------------------------------------------------------------
#define MM_KITERS 16          // 512 / 32
#define MMS 36                // padded row stride in floats
#define MM_TILE_W (128 * MMS) // words per tile (4608)
#define MM_BUF_W (2 * MM_TILE_W)
#define MM_SMEM_BYTES (2 * MM_BUF_W * 4)   // 73728

__device__ __forceinline__ uint32_t f2tf32(float f) {
    uint32_t r;
    asm("cvt.rna.tf32.f32 %0, %1;" : "=r"(r) : "f"(f));
    return r;
}
__device__ __forceinline__ void mma_tf32(float* c, const uint32_t* a,
                                         const uint32_t* b) {
    asm volatile(
        "mma.sync.aligned.m16n8k8.row.col.f32.tf32.tf32.f32 "
        "{%0,%1,%2,%3}, {%4,%5,%6,%7}, {%8,%9}, {%0,%1,%2,%3};"
        : "+f"(c[0]), "+f"(c[1]), "+f"(c[2]), "+f"(c[3])
        : "r"(a[0]), "r"(a[1]), "r"(a[2]), "r"(a[3]), "r"(b[0]), "r"(b[1]));
}

template <int OUTLD>
__global__ __launch_bounds__(256, 2) void gemm_mma_kernel(
    const float* __restrict__ Wm,    // [N][512]
    const float* __restrict__ bias,  // [N]
    float* __restrict__ outp)
{
    extern __shared__ uint32_t smem[];   // [2 bufs][A tile | B tile]
    const int tid = threadIdx.x;
    const int w = tid >> 5;
    const int lane = tid & 31;
    const int g = lane >> 2;   // groupID
    const int t = lane & 3;    // threadID_in_group
    const int wm = w >> 2;     // 0..1
    const int wn = w & 3;      // 0..3
    const int by = blockIdx.y;
    const int m0 = by * 128;
    const int n0 = blockIdx.x * 128;

    // Coalesced global bases: thread covers rows (tid>>3) + q*32, cols (tid&7)*4
    // A[m][k] = g_hs[((m&255)*32 + (m>>8))*512 + k]; local row r -> +r*16384
    const float* aG = g_hs +
        ((size_t)((by & 1) * 128) * 32 + (size_t)(by >> 1)) * 512 +
        (size_t)(tid >> 3) * 16384 + (tid & 7) * 4;
    const float* bG = Wm + (size_t)(n0 + (tid >> 3)) * 512 + (tid & 7) * 4;

    // Staging smem word offset (row-major, padded stride MMS)
    const uint32_t stg = (uint32_t)(tid >> 3) * MMS + (uint32_t)(tid & 7) * 4;

    float c[4][4][4];
#pragma unroll
    for (int mi = 0; mi < 4; mi++)
#pragma unroll
        for (int ni = 0; ni < 4; ni++)
#pragma unroll
            for (int q = 0; q < 4; q++) c[mi][ni][q] = 0.f;

    float4 ra[4], rb[4];

    auto GATHER = [&](int s) {
        const int k0 = s * 32;
#pragma unroll
        for (int q = 0; q < 4; q++)
            ra[q] = *(const float4*)(aG + (size_t)q * 32 * 16384 + k0);
#pragma unroll
        for (int q = 0; q < 4; q++)
            rb[q] = *(const float4*)(bG + (size_t)q * 32 * 512 + k0);
    };
    auto STORE = [&](int buf) {
        uint32_t* aD = smem + buf * MM_BUF_W + stg;
        uint32_t* bD = aD + MM_TILE_W;
#pragma unroll
        for (int q = 0; q < 4; q++) {
            uint4 v = make_uint4(f2tf32(ra[q].x), f2tf32(ra[q].y),
                                 f2tf32(ra[q].z), f2tf32(ra[q].w));
            *(uint4*)(aD + q * 32 * MMS) = v;
            uint4 u = make_uint4(f2tf32(rb[q].x), f2tf32(rb[q].y),
                                 f2tf32(rb[q].z), f2tf32(rb[q].w));
            *(uint4*)(bD + q * 32 * MMS) = u;
        }
    };

    GATHER(0);
    STORE(0);
    __syncthreads();

    for (int s = 0; s < MM_KITERS; s++) {
        const int cur = s & 1;
        if (s + 1 < MM_KITERS) GATHER(s + 1);

        // Conflict-free LDS.32 consumer pointers
        const uint32_t* aC = smem + cur * MM_BUF_W + (wm * 64 + g) * MMS + t;
        const uint32_t* bC = smem + cur * MM_BUF_W + MM_TILE_W +
                             (wn * 32 + g) * MMS + t;
#pragma unroll
        for (int kk = 0; kk < 4; kk++) {
            uint32_t af[4][4];
#pragma unroll
            for (int mi = 0; mi < 4; mi++) {
                const uint32_t* p = aC + mi * (16 * MMS) + kk * 8;
                af[mi][0] = p[0];           // (g,   t)
                af[mi][1] = p[8 * MMS];     // (g+8, t)
                af[mi][2] = p[4];           // (g,   t+4)
                af[mi][3] = p[8 * MMS + 4]; // (g+8, t+4)
            }
            uint32_t bf[4][2];
#pragma unroll
            for (int ni = 0; ni < 4; ni++) {
                const uint32_t* p = bC + ni * (8 * MMS) + kk * 8;
                bf[ni][0] = p[0];   // B[k=t][n=g]
                bf[ni][1] = p[4];   // B[k=t+4][n=g]
            }
#pragma unroll
            for (int mi = 0; mi < 4; mi++)
#pragma unroll
                for (int ni = 0; ni < 4; ni++)
                    mma_tf32(c[mi][ni], af[mi], bf[ni]);
        }

        if (s + 1 < MM_KITERS) {
            STORE((s + 1) & 1);
            __syncthreads();
        }
    }

    // Epilogue: direct STG.64 with bias
    const int row0 = m0 + wm * 64 + g;
    const int col0 = n0 + wn * 32 + 2 * t;
    float2 bias2[4];
#pragma unroll
    for (int ni = 0; ni < 4; ni++)
        bias2[ni] = *(const float2*)(bias + col0 + ni * 8);
#pragma unroll
    for (int mi = 0; mi < 4; mi++) {
        float* r0 = outp + (size_t)(row0 + mi * 16) * OUTLD;
        float* r1 = outp + (size_t)(row0 + mi * 16 + 8) * OUTLD;
#pragma unroll
        for (int ni = 0; ni < 4; ni++) {
            float2 v0 = make_float2(c[mi][ni][0] + bias2[ni].x,
                                    c[mi][ni][1] + bias2[ni].y);
            float2 v1 = make_float2(c[mi][ni][2] + bias2[ni].x,
                                    c[mi][ni][3] + bias2[ni].y);
            *(float2*)(r0 + col0 + ni * 8) = v0;
            *(float2*)(r1 + col0 + ni * 8) = v1;
        }
    }
}

// ---------------------------------------------------------------------------
// Persistent LSTM kernel (unchanged — correct & ~0.9ms)
// ---------------------------------------------------------------------------
#define LSTM_BLOCKS 128
#define LSTM_SMEM_FLOATS (32 * 512 + 16 * 32 * 16 + 16 * 32 + 4 * 32 + 16)
#define LSTM_SMEM_BYTES (LSTM_SMEM_FLOATS * 4)

__device__ __forceinline__ int lstm_grow(int j0, int r) {
    return (r >> 2) * 512 + j0 + (r & 3);
}

__device__ __forceinline__ void grid_barrier() {
    __threadfence();
    __syncthreads();
    if (threadIdx.x == 0) {
        unsigned gen = g_bar_gen;
        unsigned arr = atomicAdd(&g_bar_count, 1u);
        if (arr == gridDim.x - 1) {
            g_bar_count = 0;
            __threadfence();
            g_bar_gen = gen + 1;
        } else {
            while (g_bar_gen == gen) { }
        }
    }
    __syncthreads();
    __threadfence();
}

__global__ __launch_bounds__(256) void lstm_kernel(const float* __restrict__ w_hh,
                                                   const float* __restrict__ b_hh) {
    extern __shared__ float sm[];
    float* sH    = sm;
    float* sRed  = sH + 32 * 512;
    float* sGate = sRed + 16 * 32 * 16;
    float* sC    = sGate + 16 * 32;
    float* sBh   = sC + 4 * 32;

    const int tid = threadIdx.x;
    const int bid = blockIdx.x;
    const int j0 = bid * 4;
    const int ks = tid & 15;
    const int rp = (tid >> 4) & 7;
    const int bh = tid >> 7;
    const int r0 = rp * 2, r1 = rp * 2 + 1;

    float w0[32], w1[32];
    {
        const float* p0 = w_hh + (size_t)lstm_grow(j0, r0) * 512 + ks;
        const float* p1 = w_hh + (size_t)lstm_grow(j0, r1) * 512 + ks;
#pragma unroll
        for (int i = 0; i < 32; i++) {
            w0[i] = p0[i * 16];
            w1[i] = p1[i * 16];
        }
    }
    if (tid < 16) sBh[tid] = b_hh[lstm_grow(j0, tid)];
    if (tid < 128) sC[tid] = 0.f;
    for (int i = tid; i < 32 * 512; i += 256) sH[i] = 0.f;
    __syncthreads();

    for (int t = 0; t < TT; t++) {
        if (t > 0) {
            const float4* src = (const float4*)(g_hs + (size_t)(t - 1) * 32 * 512);
            float4* dst = (float4*)sH;
#pragma unroll
            for (int i = 0; i < 16; i++) dst[tid + 256 * i] = src[tid + 256 * i];
            __syncthreads();
        }

        float acc0[16], acc1[16];
#pragma unroll
        for (int b = 0; b < 16; b++) { acc0[b] = 0.f; acc1[b] = 0.f; }
#pragma unroll
        for (int i = 0; i < 32; i++) {
            const float* hp = sH + bh * 16 * 512 + ks + 16 * i;
            const float wa = w0[i];
            const float wb = w1[i];
#pragma unroll
            for (int b = 0; b < 16; b++) {
                float hv = hp[b * 512];
                acc0[b] = fmaf(wa, hv, acc0[b]);
                acc1[b] = fmaf(wb, hv, acc1[b]);
            }
        }
#pragma unroll
        for (int b = 0; b < 16; b++) {
            int bb = bh * 16 + b;
            sRed[(r0 * 32 + bb) * 16 + ks] = acc0[b];
            sRed[(r1 * 32 + bb) * 16 + ks] = acc1[b];
        }
        __syncthreads();

#pragma unroll
        for (int o2 = 0; o2 < 2; o2++) {
            int o = tid * 2 + o2;
            int r = o >> 5, b = o & 31;
            const float* pr = sRed + o * 16;
            float s = 0.f;
#pragma unroll
            for (int j = 0; j < 16; j++) s += pr[j];
            s += g_xg[(size_t)(t * 32 + b) * G4 + lstm_grow(j0, r)] + sBh[r];
            sGate[o] = s;
        }
        __syncthreads();

        if (tid < 128) {
            int u = tid & 3, b = tid >> 2;
            float gi = sGate[(0 + u) * 32 + b];
            float gf = sGate[(4 + u) * 32 + b];
            float gg = sGate[(8 + u) * 32 + b];
            float go = sGate[(12 + u) * 32 + b];
            float c = sC[u * 32 + b];
            float si = 1.f / (1.f + expf(-gi));
            float sf = 1.f / (1.f + expf(-gf));
            float so = 1.f / (1.f + expf(-go));
            c = sf * c + si * tanhf(gg);
            float h = so * tanhf(c);
            sC[u * 32 + b] = c;
            g_hs[(size_t)(t * 32 + b) * 512 + j0 + u] = h;
        }
        grid_barrier();
    }
}

// ---------------------------------------------------------------------------
// Launch
// ---------------------------------------------------------------------------
extern "C" void kernel_launch(void* const* d_in, const int* in_sizes, int n_in,
                              void* d_out, int out_size) {
    const void*  x       = d_in[0];
    const float* embed_w = (const float*)d_in[1];
    const float* w_ih    = (const float*)d_in[2];
    const float* w_hh    = (const float*)d_in[3];
    const float* b_ih    = (const float*)d_in[4];
    const float* b_hh    = (const float*)d_in[5];
    const float* fc_w    = (const float*)d_in[6];
    const float* fc_b    = (const float*)d_in[7];
    const float* ln_w    = (const float*)d_in[8];
    const float* ln_b    = (const float*)d_in[9];

    float* out    = (float*)d_out;
    float* states = out + (size_t)BT * VV;

    // 1) decode token indices
    decode_idx_kernel<<<BT / 256, 256>>>(x);

    // 2) xg = embed[x] @ w_ih^T + b_ih   (SIMT fp32, keeps LSTM inputs exact)
    gemm_xg_kernel<<<dim3(G4 / 128, BT / 128), 256>>>(w_ih, b_ih, embed_w);

    // 3) sequential LSTM
    cudaFuncSetAttribute(lstm_kernel, cudaFuncAttributeMaxDynamicSharedMemorySize,
                         LSTM_SMEM_BYTES);
    lstm_kernel<<<LSTM_BLOCKS, 256, LSTM_SMEM_BYTES>>>(w_hh, b_hh);

    // 4) out = hs @ fc_w^T + fc_b   (mma.sync tf32, coalesced staging)
    cudaFuncSetAttribute(gemm_mma_kernel<VV>,
                         cudaFuncAttributeMaxDynamicSharedMemorySize, MM_SMEM_BYTES);
    gemm_mma_kernel<VV><<<dim3(VV / 128, BT / 128), 256, MM_SMEM_BYTES>>>(
        fc_w, fc_b, out);

    // 5) states = hs @ ln_w^T + ln_b   (mma.sync tf32)
    cudaFuncSetAttribute(gemm_mma_kernel<HH>,
                         cudaFuncAttributeMaxDynamicSharedMemorySize, MM_SMEM_BYTES);
    gemm_mma_kernel<HH><<<dim3(HH / 128, BT / 128), 256, MM_SMEM_BYTES>>>(
        ln_w, ln_b, states);
}